// round 12
// baseline (speedup 1.0000x reference)
#include <cuda_runtime.h>
#include <math_constants.h>
#include <stdint.h>

// PQHead: out[b, m*6+d] = codebooks[m, argmax_k <x[b,m*6:...], cb[m,k,:]>, d]
// (forward value of the straight-through estimator == discrete codeword)
//
// FROZEN NUMERICS: dot = x0*c0 then fma.rn chain d=1..5 (scalar FFMA), argmax
// exact, FIRST-max tie rule. Zero flips vs JAX reference at this order.
//
// LESSONS:
//  R3/R4: reg-cap spills -> 8x DRAM. R7: f32x2 half-rate -> banned.
//  R8: no prefetch -> tile-head LDG stalls. R9: prefetch+RPT2, 63us,
//      L1TEX 84% = wall (cb LDS 3 cyc/pair). R10: RPT4@24warps -> latency bound.
//  R11: QM=8 alone worsened LDG sector spray.
//  R12: cp.async double-buffer removes the 24 prefetch regs -> RPT=4 fits
//       the 4-CTA/64-reg budget: 32 warps + prefetch + 1.5cyc/pair cb LDS.

#define B_ROWS   32768
#define M_SUB    128
#define QM       8                       // m's per block
#define NGRP     (M_SUB / QM)            // 16
#define K_CODES  32
#define D_SUB    6
#define DIM      768
#define RPT      4                       // rows per thread
#define TPB      256                     // 32 row-groups x 8 m
#define TILE_ROWS (RPT * (TPB / QM))     // 128
#define NTILES   (B_ROWS / TILE_ROWS)    // 256 per group
#define BLK_PER_G 37                     // 16 x 37 = 592 = 4/SM
#define NBLOCKS  (NGRP * BLK_PER_G)
#define ROW_B    (QM * D_SUB * 4)        // 192 bytes of x per row per group
#define XBUF_B   (TILE_ROWS * ROW_B)     // 24576 bytes per buffer
#define SMEM_B   (2 * XBUF_B + K_CODES * QM * 16 + K_CODES * QM * 8)  // 55296

__device__ __forceinline__ void cp16(void* dst_smem, const void* src) {
    uint32_t d = (uint32_t)__cvta_generic_to_shared(dst_smem);
    asm volatile("cp.async.cg.shared.global [%0], [%1], 16;" :: "r"(d), "l"(src));
}

__global__ void __launch_bounds__(TPB, 4)
pq_head_kernel(const float* __restrict__ x,
               const float* __restrict__ cb,
               float* __restrict__ out)
{
    extern __shared__ char smem[];
    float* xbuf0 = reinterpret_cast<float*>(smem);
    float* xbuf1 = reinterpret_cast<float*>(smem + XBUF_B);
    float4* cbA  = reinterpret_cast<float4*>(smem + 2 * XBUF_B);
    float2* cbB  = reinterpret_cast<float2*>(smem + 2 * XBUF_B + K_CODES * QM * 16);

    const int t = threadIdx.x;
    const int grp = blockIdx.x / BLK_PER_G;
    const int bstart = blockIdx.x % BLK_PER_G;

    // One-time codebook load for this group.
    {
        const float* cbg = cb + (size_t)grp * QM * (K_CODES * D_SUB);
        for (int i = t; i < QM * K_CODES; i += TPB) {
            int mloc = i / K_CODES;
            int k    = i - mloc * K_CODES;
            const float* src = cbg + (size_t)mloc * (K_CODES * D_SUB) + k * D_SUB;
            cbA[k * QM + mloc] = make_float4(src[0], src[1], src[2], src[3]);
            cbB[k * QM + mloc] = make_float2(src[4], src[5]);
        }
    }

    // cp.async copy of one tile: thread t copies half a row (96B = 6x16B).
    const int cprow  = t >> 1;
    const int cphalf = (t & 1) * 96;          // byte offset within the row
    const float* xg_base = x + (size_t)grp * QM * D_SUB;   // col0 of this group

    auto issue_tile = [&](float* buf, int tile) {
        const char* src = reinterpret_cast<const char*>(
            xg_base + (size_t)(tile * TILE_ROWS + cprow) * DIM) + cphalf;
        char* dst = reinterpret_cast<char*>(buf) + cprow * ROW_B + cphalf;
        #pragma unroll
        for (int j = 0; j < 6; j++)
            cp16(dst + j * 16, src + j * 16);
        asm volatile("cp.async.commit_group;");
    };

    // Prologue: start first tile's copy (codebook STS drains under it).
    issue_tile(xbuf0, bstart);

    const int mloc = t & (QM - 1);
    const int g    = t >> 3;                  // row-group 0..31
    const int col0 = (grp * QM + mloc) * D_SUB;
    const int xoff = g * RPT * (ROW_B / 4) + mloc * D_SUB;  // float offset in buf

    float* bufs[2] = {xbuf0, xbuf1};
    int parity = 0;

    for (int tile = bstart; tile < NTILES; tile += BLK_PER_G) {
        // Kick off next tile's copy into the other buffer (clamped at end).
        int nt = tile + BLK_PER_G;
        issue_tile(bufs[parity ^ 1], (nt < NTILES) ? nt : tile);

        // Wait for current tile (<=1 group left pending = the one just issued).
        asm volatile("cp.async.wait_group 1;");
        __syncthreads();

        // Load this thread's RPT rows from smem (3x LDS.64 per row).
        const float* bp = bufs[parity] + xoff;
        float xv[RPT][D_SUB];
        #pragma unroll
        for (int r = 0; r < RPT; r++) {
            const float2* p = reinterpret_cast<const float2*>(bp + r * (ROW_B / 4));
            float2 a = p[0], bq = p[1], c = p[2];
            xv[r][0] = a.x;  xv[r][1] = a.y;
            xv[r][2] = bq.x; xv[r][3] = bq.y;
            xv[r][4] = c.x;  xv[r][5] = c.y;
        }
        __syncthreads();   // all reads done -> next iter may overwrite this buf

        float best[RPT];
        int   idx[RPT];
        #pragma unroll
        for (int r = 0; r < RPT; r++) { best[r] = -CUDART_INF_F; idx[r] = 0; }

        // Bounded unroll keeps the live set under the 64-reg cap.
        #pragma unroll 2
        for (int k = 0; k < K_CODES; k++) {
            const float4 ca  = cbA[k * QM + mloc];
            const float2 cbv = cbB[k * QM + mloc];
            #pragma unroll
            for (int r = 0; r < RPT; r++) {
                float dot = xv[r][0] * ca.x;
                dot = fmaf(xv[r][1], ca.y, dot);
                dot = fmaf(xv[r][2], ca.z, dot);
                dot = fmaf(xv[r][3], ca.w, dot);
                dot = fmaf(xv[r][4], cbv.x, dot);
                dot = fmaf(xv[r][5], cbv.y, dot);
                // EXACT argmax, FIRST-max tie rule; FMNMX value chain keeps
                // the predicate latency off the loop-carried path.
                bool p  = dot > best[r];
                best[r] = fmaxf(best[r], dot);
                idx[r]  = p ? k : idx[r];
            }
        }

        // Emit the winning codeword rows.
        float* op = out + (size_t)(tile * TILE_ROWS + g * RPT) * DIM + col0;
        #pragma unroll
        for (int r = 0; r < RPT; r++) {
            const float4 oa = cbA[idx[r] * QM + mloc];
            const float2 ob = cbB[idx[r] * QM + mloc];
            float2* po = reinterpret_cast<float2*>(op + (size_t)r * DIM);
            po[0] = make_float2(oa.x, oa.y);
            po[1] = make_float2(oa.z, oa.w);
            po[2] = ob;
        }

        parity ^= 1;
    }

    // Drain outstanding copies before exit.
    asm volatile("cp.async.wait_group 0;");
}

extern "C" void kernel_launch(void* const* d_in, const int* in_sizes, int n_in,
                              void* d_out, int out_size)
{
    const float* x  = (const float*)d_in[0];
    const float* cb = (const float*)d_in[1];
    float* out      = (float*)d_out;

    cudaFuncSetAttribute(pq_head_kernel,
                         cudaFuncAttributeMaxDynamicSharedMemorySize, SMEM_B);
    pq_head_kernel<<<NBLOCKS, TPB, SMEM_B>>>(x, cb, out);
}